// round 11
// baseline (speedup 1.0000x reference)
#include <cuda_runtime.h>
#include <cuda_bf16.h>
#include <cuda_fp16.h>
#include <cstdint>
#include <cstddef>

#define NN 50000
#define NE 600000
#define NF 128
#define NG 500
#define NB_SCAN 49   // ceil(50000/1024)

// ---------------- device scratch (static, no allocation) ----------------
__device__ __half g_actA[NN * NF];    // layer activations (fp16)
__device__ __half g_actB[NN * NF];
__device__ __half g_lin16[NN * NF];   // x @ Wl  (fp16, gather-only)
__device__ float  g_root[NN * NF];    // x @ Wr
__device__ int    g_deg[NN];
__device__ int    g_off[NN + 1];
__device__ int    g_cur[NN];
__device__ int    g_esrc[NE];
__device__ float  g_gsum[NG];
__device__ int    g_gcnt[NG];
__device__ int    g_bsum[64];
__device__ int    g_bpre[64];
// pre-split, pre-transposed weights: [mat][n][k] bf16, mat = layer*2 + (0:Wl,1:Wr)
__device__ __nv_bfloat16 g_Wt_hi[6 * 128 * 128];
__device__ __nv_bfloat16 g_Wt_lo[6 * 128 * 128];

__device__ __forceinline__ void bsplit(float v, uint16_t& h, uint16_t& l) {
    __nv_bfloat16 hb = __float2bfloat16_rn(v);
    float hf = __bfloat162float(hb);
    __nv_bfloat16 lb = __float2bfloat16_rn(v - hf);
    h = __bfloat16_as_ushort(hb);
    l = __bfloat16_as_ushort(lb);
}
__device__ __forceinline__ uint32_t pack2(uint16_t a, uint16_t b) {
    return (uint32_t)a | ((uint32_t)b << 16);
}

// ---------------- weight prep ----------------
__global__ void prep_w_kernel(const float* W0, const float* W1, const float* W2,
                              const float* W3, const float* W4, const float* W5) {
    const float* Ws[6] = { W0, W1, W2, W3, W4, W5 };
    int mat = blockIdx.y;
    const float* W = Ws[mat];
    int i = blockIdx.x * blockDim.x + threadIdx.x;   // 0..16383
    int k = i >> 7, n = i & 127;
    float v = W[i];
    uint16_t h, l;
    bsplit(v, h, l);
    int o = mat * 16384 + n * 128 + k;
    g_Wt_hi[o] = __ushort_as_bfloat16(h);
    g_Wt_lo[o] = __ushort_as_bfloat16(l);
}

// ---------------- CSR build ----------------
__global__ void zero_kernel() {
    int i = blockIdx.x * blockDim.x + threadIdx.x;
    if (i < NN) g_deg[i] = 0;
    if (i < NG) { g_gcnt[i] = 0; g_gsum[i] = 0.0f; }
}

__global__ void hist_kernel(const int* __restrict__ ei, const int* __restrict__ batch) {
    int idx = blockIdx.x * blockDim.x + threadIdx.x;
    if (idx < NE / 4) {
        int4 d4 = ((const int4*)(ei + NE))[idx];
        if (d4.x >= 0 && d4.x < NN) atomicAdd(&g_deg[d4.x], 1);
        if (d4.y >= 0 && d4.y < NN) atomicAdd(&g_deg[d4.y], 1);
        if (d4.z >= 0 && d4.z < NN) atomicAdd(&g_deg[d4.z], 1);
        if (d4.w >= 0 && d4.w < NN) atomicAdd(&g_deg[d4.w], 1);
    }
    if (idx < NN / 4) {
        int4 b4 = ((const int4*)batch)[idx];
        if (b4.x >= 0 && b4.x < NG) atomicAdd(&g_gcnt[b4.x], 1);
        if (b4.y >= 0 && b4.y < NG) atomicAdd(&g_gcnt[b4.y], 1);
        if (b4.z >= 0 && b4.z < NG) atomicAdd(&g_gcnt[b4.z], 1);
        if (b4.w >= 0 && b4.w < NG) atomicAdd(&g_gcnt[b4.w], 1);
    }
}

__global__ __launch_bounds__(1024) void scan1_kernel() {
    __shared__ int warpsum[32];
    int tid = threadIdx.x, lane = tid & 31, wid = tid >> 5;
    int i = blockIdx.x * 1024 + tid;
    int v = (i < NN) ? g_deg[i] : 0;
    int x = v;
    #pragma unroll
    for (int o = 1; o < 32; o <<= 1) {
        int t = __shfl_up_sync(0xFFFFFFFFu, x, o);
        if (lane >= o) x += t;
    }
    if (lane == 31) warpsum[wid] = x;
    __syncthreads();
    if (wid == 0) {
        int y = warpsum[lane];
        #pragma unroll
        for (int o = 1; o < 32; o <<= 1) {
            int t = __shfl_up_sync(0xFFFFFFFFu, y, o);
            if (lane >= o) y += t;
        }
        warpsum[lane] = y;
    }
    __syncthreads();
    int wprefix = (wid > 0) ? warpsum[wid - 1] : 0;
    if (i < NN) g_off[i] = x - v + wprefix;
    if (tid == 1023) g_bsum[blockIdx.x] = wprefix + x;
}

__global__ void scan2_kernel() {
    int lane = threadIdx.x;
    int v0 = (lane < NB_SCAN) ? g_bsum[lane] : 0;
    int x0 = v0;
    #pragma unroll
    for (int o = 1; o < 32; o <<= 1) {
        int t = __shfl_up_sync(0xFFFFFFFFu, x0, o);
        if (lane >= o) x0 += t;
    }
    int tot0 = __shfl_sync(0xFFFFFFFFu, x0, 31);
    int i1 = lane + 32;
    int v1 = (i1 < NB_SCAN) ? g_bsum[i1] : 0;
    int x1 = v1;
    #pragma unroll
    for (int o = 1; o < 32; o <<= 1) {
        int t = __shfl_up_sync(0xFFFFFFFFu, x1, o);
        if (lane >= o) x1 += t;
    }
    g_bpre[lane] = x0 - v0;
    g_bpre[i1] = x1 - v1 + tot0;
    if (lane == 0) g_off[NN] = NE;
}

__global__ __launch_bounds__(1024) void scan3_kernel() {
    int i = blockIdx.x * 1024 + threadIdx.x;
    if (i < NN) {
        int o = g_off[i] + g_bpre[blockIdx.x];
        g_off[i] = o;
        g_cur[i] = o;
    }
}

__global__ void scatter_kernel(const int* __restrict__ ei) {
    int idx = blockIdx.x * blockDim.x + threadIdx.x;
    if (idx < NE / 4) {
        int4 s4 = ((const int4*)ei)[idx];
        int4 d4 = ((const int4*)(ei + NE))[idx];
        if (d4.x >= 0 && d4.x < NN) g_esrc[atomicAdd(&g_cur[d4.x], 1)] = s4.x;
        if (d4.y >= 0 && d4.y < NN) g_esrc[atomicAdd(&g_cur[d4.y], 1)] = s4.y;
        if (d4.z >= 0 && d4.z < NN) g_esrc[atomicAdd(&g_cur[d4.z], 1)] = s4.z;
        if (d4.w >= 0 && d4.w < NN) g_esrc[atomicAdd(&g_cur[d4.w], 1)] = s4.w;
    }
}

// ---------------- bf16x2 tensor-core GEMM --------------------------------------
// M-tile 64, N=128. blockIdx.y: 0 -> g_lin16 (Wl, fp16 out), 1 -> g_root (Wr, fp32)
// A source: layer 0 = fp32 X; layers 1,2 = fp16 activations (exact bf16 hi/lo split)
#define MT 64
#define SA 136
#define SB 136
#define A_ELEMS (64 * SA)
#define B_ELEMS (128 * SB)
#define GEMM_SMEM ((2 * A_ELEMS + 2 * B_ELEMS) * 2)   // 104448 bytes

__device__ __forceinline__ void mma_bf16(float* c, const uint32_t* a, const uint32_t* b) {
    asm volatile(
        "mma.sync.aligned.m16n8k16.row.col.f32.bf16.bf16.f32 "
        "{%0,%1,%2,%3}, {%4,%5,%6,%7}, {%8,%9}, {%0,%1,%2,%3};"
        : "+f"(c[0]), "+f"(c[1]), "+f"(c[2]), "+f"(c[3])
        : "r"(a[0]), "r"(a[1]), "r"(a[2]), "r"(a[3]), "r"(b[0]), "r"(b[1]));
}

__global__ __launch_bounds__(256, 2) void gemm2_kernel(int layer,
                                                       const float* __restrict__ X) {
    extern __shared__ uint16_t sm16[];
    uint16_t* Ah = sm16;
    uint16_t* Al = Ah + A_ELEMS;
    uint16_t* Bh = Al + A_ELEMS;
    uint16_t* Bl = Bh + B_ELEMS;

    int mat = layer * 2 + blockIdx.y;
    const __nv_bfloat16* wt_h = g_Wt_hi + mat * 16384;
    const __nv_bfloat16* wt_l = g_Wt_lo + mat * 16384;

    int tid = threadIdx.x, lane = tid & 31, wid = tid >> 5;
    int row0 = blockIdx.x * MT;

    // ---- fill A (64x128 -> bf16 hi/lo) ----
    #pragma unroll
    for (int i = 0; i < 8; i++) {
        int slot = tid + i * 256;
        int r = slot >> 5;
        int c = (slot & 31) << 2;
        float4 v = make_float4(0.f, 0.f, 0.f, 0.f);
        if (row0 + r < NN) {
            if (layer == 0) {
                v = *(const float4*)(X + (size_t)(row0 + r) * NF + c);
            } else {
                const __half* act = (layer == 1) ? g_actA : g_actB;
                uint2 p = *(const uint2*)(act + (size_t)(row0 + r) * NF + c);
                float2 f01 = __half22float2(*(__half2*)&p.x);
                float2 f23 = __half22float2(*(__half2*)&p.y);
                v = make_float4(f01.x, f01.y, f23.x, f23.y);
            }
        }
        uint16_t hx, lx, hy, ly, hz, lz, hw, lw;
        bsplit(v.x, hx, lx); bsplit(v.y, hy, ly);
        bsplit(v.z, hz, lz); bsplit(v.w, hw, lw);
        uint2 hp, lp;
        hp.x = pack2(hx, hy); hp.y = pack2(hz, hw);
        lp.x = pack2(lx, ly); lp.y = pack2(lz, lw);
        *(uint2*)&Ah[r * SA + c] = hp;
        *(uint2*)&Al[r * SA + c] = lp;
    }
    #pragma unroll
    for (int i = 0; i < 8; i++) {
        int slot = tid + i * 256;
        int n = slot >> 4;
        int c8 = (slot & 15) << 3;
        *(uint4*)&Bh[n * SB + c8] = *(const uint4*)&wt_h[n * 128 + c8];
        *(uint4*)&Bl[n * SB + c8] = *(const uint4*)&wt_l[n * 128 + c8];
    }
    __syncthreads();

    int warp_m = wid >> 2;
    int warp_n = wid & 3;
    int m_base = warp_m * 32;
    int n_base = warp_n * 32;
    int g = lane >> 2;
    int t = lane & 3;

    float c[2][4][4];
    #pragma unroll
    for (int mi = 0; mi < 2; mi++)
        #pragma unroll
        for (int ni = 0; ni < 4; ni++)
            #pragma unroll
            for (int j = 0; j < 4; j++) c[mi][ni][j] = 0.0f;

    #pragma unroll
    for (int ks = 0; ks < 8; ks++) {
        int k0 = ks * 16;
        uint32_t ah[2][4], al[2][4];
        #pragma unroll
        for (int mi = 0; mi < 2; mi++) {
            int r = m_base + mi * 16 + g;
            ah[mi][0] = *(const uint32_t*)&Ah[r * SA + k0 + 2 * t];
            ah[mi][1] = *(const uint32_t*)&Ah[(r + 8) * SA + k0 + 2 * t];
            ah[mi][2] = *(const uint32_t*)&Ah[r * SA + k0 + 2 * t + 8];
            ah[mi][3] = *(const uint32_t*)&Ah[(r + 8) * SA + k0 + 2 * t + 8];
            al[mi][0] = *(const uint32_t*)&Al[r * SA + k0 + 2 * t];
            al[mi][1] = *(const uint32_t*)&Al[(r + 8) * SA + k0 + 2 * t];
            al[mi][2] = *(const uint32_t*)&Al[r * SA + k0 + 2 * t + 8];
            al[mi][3] = *(const uint32_t*)&Al[(r + 8) * SA + k0 + 2 * t + 8];
        }
        uint32_t bh[4][2], blo[4][2];
        #pragma unroll
        for (int ni = 0; ni < 4; ni++) {
            int n = n_base + ni * 8 + g;
            bh[ni][0]  = *(const uint32_t*)&Bh[n * SB + k0 + 2 * t];
            bh[ni][1]  = *(const uint32_t*)&Bh[n * SB + k0 + 2 * t + 8];
            blo[ni][0] = *(const uint32_t*)&Bl[n * SB + k0 + 2 * t];
            blo[ni][1] = *(const uint32_t*)&Bl[n * SB + k0 + 2 * t + 8];
        }
        #pragma unroll
        for (int mi = 0; mi < 2; mi++)
            #pragma unroll
            for (int ni = 0; ni < 4; ni++) {
                mma_bf16(c[mi][ni], ah[mi], bh[ni]);
                mma_bf16(c[mi][ni], ah[mi], blo[ni]);
                mma_bf16(c[mi][ni], al[mi], bh[ni]);
            }
    }

    if (blockIdx.y == 0) {
        #pragma unroll
        for (int mi = 0; mi < 2; mi++) {
            int r0 = row0 + m_base + mi * 16 + g;
            int r1 = r0 + 8;
            #pragma unroll
            for (int ni = 0; ni < 4; ni++) {
                int col = n_base + ni * 8 + 2 * t;
                if (r0 < NN)
                    *(__half2*)(g_lin16 + (size_t)r0 * NF + col) =
                        __floats2half2_rn(c[mi][ni][0], c[mi][ni][1]);
                if (r1 < NN)
                    *(__half2*)(g_lin16 + (size_t)r1 * NF + col) =
                        __floats2half2_rn(c[mi][ni][2], c[mi][ni][3]);
            }
        }
    } else {
        #pragma unroll
        for (int mi = 0; mi < 2; mi++) {
            int r0 = row0 + m_base + mi * 16 + g;
            int r1 = r0 + 8;
            #pragma unroll
            for (int ni = 0; ni < 4; ni++) {
                int col = n_base + ni * 8 + 2 * t;
                if (r0 < NN)
                    *(float2*)(g_root + (size_t)r0 * NF + col) = make_float2(c[mi][ni][0], c[mi][ni][1]);
                if (r1 < NN)
                    *(float2*)(g_root + (size_t)r1 * NF + col) = make_float2(c[mi][ni][2], c[mi][ni][3]);
            }
        }
    }
}

// ---------------- aggregation: warp-per-node, fp16 gather, unroll 4 --------------
// output activations stored fp16 (exactly splittable into bf16 hi/lo next layer)
__global__ __launch_bounds__(256) void agg_kernel(int layer, int last,
                                                  const float* __restrict__ bl,
                                                  const float* __restrict__ Wout,
                                                  const int* __restrict__ batch) {
    __half* xout = (layer == 1) ? g_actB : g_actA;
    int wid = threadIdx.x >> 5, lane = threadIdx.x & 31;
    int n = blockIdx.x * 8 + wid;
    if (n >= NN) return;
    int beg = g_off[n], end = g_off[n + 1];
    float4 acc = make_float4(0.f, 0.f, 0.f, 0.f);
    int e = beg;
    for (; e + 4 <= end; e += 4) {
        int s0 = g_esrc[e], s1 = g_esrc[e + 1], s2 = g_esrc[e + 2], s3 = g_esrc[e + 3];
        uint2 p0 = ((const uint2*)(g_lin16 + (size_t)s0 * NF))[lane];
        uint2 p1 = ((const uint2*)(g_lin16 + (size_t)s1 * NF))[lane];
        uint2 p2 = ((const uint2*)(g_lin16 + (size_t)s2 * NF))[lane];
        uint2 p3 = ((const uint2*)(g_lin16 + (size_t)s3 * NF))[lane];
        float2 a0 = __half22float2(*(__half2*)&p0.x), b0 = __half22float2(*(__half2*)&p0.y);
        float2 a1 = __half22float2(*(__half2*)&p1.x), b1 = __half22float2(*(__half2*)&p1.y);
        float2 a2 = __half22float2(*(__half2*)&p2.x), b2 = __half22float2(*(__half2*)&p2.y);
        float2 a3 = __half22float2(*(__half2*)&p3.x), b3 = __half22float2(*(__half2*)&p3.y);
        acc.x += (a0.x + a1.x) + (a2.x + a3.x);
        acc.y += (a0.y + a1.y) + (a2.y + a3.y);
        acc.z += (b0.x + b1.x) + (b2.x + b3.x);
        acc.w += (b0.y + b1.y) + (b2.y + b3.y);
    }
    for (; e < end; e++) {
        uint2 p = ((const uint2*)(g_lin16 + (size_t)g_esrc[e] * NF))[lane];
        float2 a = __half22float2(*(__half2*)&p.x);
        float2 b = __half22float2(*(__half2*)&p.y);
        acc.x += a.x; acc.y += a.y; acc.z += b.x; acc.w += b.y;
    }
    int deg = end - beg;
    float inv = (deg > 0) ? 1.0f / (float)deg : 0.0f;
    float4 bv = *(const float4*)(bl + lane * 4);
    float4 rv = *(const float4*)(g_root + (size_t)n * NF + lane * 4);
    float4 o;
    o.x = fmaxf(acc.x * inv + bv.x + rv.x, 0.0f);
    o.y = fmaxf(acc.y * inv + bv.y + rv.y, 0.0f);
    o.z = fmaxf(acc.z * inv + bv.z + rv.z, 0.0f);
    o.w = fmaxf(acc.w * inv + bv.w + rv.w, 0.0f);
    if (!last) {
        __half2 o01 = __floats2half2_rn(o.x, o.y);
        __half2 o23 = __floats2half2_rn(o.z, o.w);
        uint2 st;
        st.x = *(uint32_t*)&o01;
        st.y = *(uint32_t*)&o23;
        *(uint2*)(xout + (size_t)n * NF + lane * 4) = st;
    } else {
        float4 w = *(const float4*)(Wout + lane * 4);
        float s = o.x * w.x + o.y * w.y + o.z * w.z + o.w * w.w;
        #pragma unroll
        for (int off = 16; off; off >>= 1) s += __shfl_xor_sync(0xFFFFFFFFu, s, off);
        if (lane == 0) {
            int b = batch[n];
            if (b >= 0 && b < NG) atomicAdd(&g_gsum[b], s);
        }
    }
}

__global__ void final_out_kernel(float* __restrict__ out, const float* __restrict__ b_out) {
    int g = blockIdx.x * blockDim.x + threadIdx.x;
    if (g < NG) {
        float c = fmaxf((float)g_gcnt[g], 1.0f);
        out[g] = g_gsum[g] / c + b_out[0];
    }
}

// ---------------- host launcher ----------------
extern "C" void kernel_launch(void* const* d_in, const int* in_sizes, int n_in,
                              void* d_out, int out_size) {
    const float* x     = (const float*)d_in[0];
    const int*   ei    = (const int*)d_in[1];
    const int*   batch = (const int*)d_in[2];
    const float* Wl[3] = { (const float*)d_in[3], (const float*)d_in[6], (const float*)d_in[9]  };
    const float* bl[3] = { (const float*)d_in[4], (const float*)d_in[7], (const float*)d_in[10] };
    const float* Wr[3] = { (const float*)d_in[5], (const float*)d_in[8], (const float*)d_in[11] };
    const float* W_out = (const float*)d_in[12];
    const float* b_out = (const float*)d_in[13];
    float* out = (float*)d_out;

    static int inited = 0;
    static cudaStream_t s2;
    static cudaEvent_t ev_fork, ev_join;
    if (!inited) {
        cudaFuncSetAttribute(gemm2_kernel, cudaFuncAttributeMaxDynamicSharedMemorySize,
                             GEMM_SMEM);
        cudaStreamCreateWithFlags(&s2, cudaStreamNonBlocking);
        cudaEventCreateWithFlags(&ev_fork, cudaEventDisableTiming);
        cudaEventCreateWithFlags(&ev_join, cudaEventDisableTiming);
        inited = 1;
    }

    // fork: CSR build chain on s2, concurrent with prep_w + gemm layer 0 on main
    cudaEventRecord(ev_fork, 0);
    cudaStreamWaitEvent(s2, ev_fork, 0);

    zero_kernel<<<(NN + 255) / 256, 256, 0, s2>>>();
    hist_kernel<<<(NE / 4 + 255) / 256, 256, 0, s2>>>(ei, batch);
    scan1_kernel<<<NB_SCAN, 1024, 0, s2>>>();
    scan2_kernel<<<1, 32, 0, s2>>>();
    scan3_kernel<<<NB_SCAN, 1024, 0, s2>>>();
    scatter_kernel<<<(NE / 4 + 255) / 256, 256, 0, s2>>>(ei);
    cudaEventRecord(ev_join, s2);

    dim3 wgrid(64, 6);
    prep_w_kernel<<<wgrid, 256>>>(Wl[0], Wr[0], Wl[1], Wr[1], Wl[2], Wr[2]);
    dim3 ggrid((NN + MT - 1) / MT, 2);
    gemm2_kernel<<<ggrid, 256, GEMM_SMEM>>>(0, x);

    // join before first aggregation (needs CSR)
    cudaStreamWaitEvent(0, ev_join, 0);

    agg_kernel<<<(NN + 7) / 8, 256>>>(0, 0, bl[0], W_out, batch);
    for (int l = 1; l < 3; l++) {
        gemm2_kernel<<<ggrid, 256, GEMM_SMEM>>>(l, x);
        agg_kernel<<<(NN + 7) / 8, 256>>>(l, (l == 2) ? 1 : 0, bl[l], W_out, batch);
    }

    final_out_kernel<<<(NG + 255) / 256, 256>>>(out, b_out);
}

// round 14
// speedup vs baseline: 1.1218x; 1.1218x over previous
#include <cuda_runtime.h>
#include <cuda_bf16.h>
#include <cuda_fp16.h>
#include <cstdint>
#include <cstddef>

#define NN 50000
#define NE 600000
#define NF 128
#define NG 500
#define NB_SCAN 49   // ceil(50000/1024)

// ---------------- device scratch (static, no allocation) ----------------
__device__ float  g_bufA[NN * NF];
__device__ float  g_bufB[NN * NF];
__device__ __half g_lin16[NN * NF];   // x @ Wl  (fp16, gather-only)
__device__ float  g_root[NN * NF];    // x @ Wr
__device__ int    g_deg[NN];
__device__ int    g_off[NN + 1];
__device__ int    g_cur[NN];
__device__ int    g_esrc[NE];
__device__ float  g_gsum[NG];
__device__ int    g_gcnt[NG];
__device__ int    g_bsum[64];
// pre-split, pre-transposed weights: [mat][n][k] bf16, mat = layer*2 + (0:Wl,1:Wr)
__device__ __nv_bfloat16 g_Wt_hi[6 * 128 * 128];
__device__ __nv_bfloat16 g_Wt_lo[6 * 128 * 128];

__device__ __forceinline__ void bsplit(float v, uint16_t& h, uint16_t& l) {
    __nv_bfloat16 hb = __float2bfloat16_rn(v);
    float hf = __bfloat162float(hb);
    __nv_bfloat16 lb = __float2bfloat16_rn(v - hf);
    h = __bfloat16_as_ushort(hb);
    l = __bfloat16_as_ushort(lb);
}
__device__ __forceinline__ uint32_t pack2(uint16_t a, uint16_t b) {
    return (uint32_t)a | ((uint32_t)b << 16);
}

// ---------------- weight prep ----------------
__global__ void prep_w_kernel(const float* W0, const float* W1, const float* W2,
                              const float* W3, const float* W4, const float* W5) {
    const float* Ws[6] = { W0, W1, W2, W3, W4, W5 };
    int mat = blockIdx.y;
    const float* W = Ws[mat];
    int i = blockIdx.x * blockDim.x + threadIdx.x;   // 0..16383
    int k = i >> 7, n = i & 127;
    float v = W[i];
    uint16_t h, l;
    bsplit(v, h, l);
    int o = mat * 16384 + n * 128 + k;
    g_Wt_hi[o] = __ushort_as_bfloat16(h);
    g_Wt_lo[o] = __ushort_as_bfloat16(l);
}

// ---------------- CSR build ----------------
__global__ void zero_kernel() {
    int i = blockIdx.x * blockDim.x + threadIdx.x;
    if (i < NN) g_deg[i] = 0;
    if (i < NG) { g_gcnt[i] = 0; g_gsum[i] = 0.0f; }
}

__global__ void hist_kernel(const int* __restrict__ ei, const int* __restrict__ batch) {
    int idx = blockIdx.x * blockDim.x + threadIdx.x;
    if (idx < NE / 4) {
        int4 d4 = ((const int4*)(ei + NE))[idx];
        if (d4.x >= 0 && d4.x < NN) atomicAdd(&g_deg[d4.x], 1);
        if (d4.y >= 0 && d4.y < NN) atomicAdd(&g_deg[d4.y], 1);
        if (d4.z >= 0 && d4.z < NN) atomicAdd(&g_deg[d4.z], 1);
        if (d4.w >= 0 && d4.w < NN) atomicAdd(&g_deg[d4.w], 1);
    }
    if (idx < NN / 4) {
        int4 b4 = ((const int4*)batch)[idx];
        if (b4.x >= 0 && b4.x < NG) atomicAdd(&g_gcnt[b4.x], 1);
        if (b4.y >= 0 && b4.y < NG) atomicAdd(&g_gcnt[b4.y], 1);
        if (b4.z >= 0 && b4.z < NG) atomicAdd(&g_gcnt[b4.z], 1);
        if (b4.w >= 0 && b4.w < NG) atomicAdd(&g_gcnt[b4.w], 1);
    }
}

// P1: per-block local scan of 1024, emit block total
__global__ __launch_bounds__(1024) void scan1_kernel() {
    __shared__ int warpsum[32];
    int tid = threadIdx.x, lane = tid & 31, wid = tid >> 5;
    int i = blockIdx.x * 1024 + tid;
    int v = (i < NN) ? g_deg[i] : 0;
    int x = v;
    #pragma unroll
    for (int o = 1; o < 32; o <<= 1) {
        int t = __shfl_up_sync(0xFFFFFFFFu, x, o);
        if (lane >= o) x += t;
    }
    if (lane == 31) warpsum[wid] = x;
    __syncthreads();
    if (wid == 0) {
        int y = warpsum[lane];
        #pragma unroll
        for (int o = 1; o < 32; o <<= 1) {
            int t = __shfl_up_sync(0xFFFFFFFFu, y, o);
            if (lane >= o) y += t;
        }
        warpsum[lane] = y;
    }
    __syncthreads();
    int wprefix = (wid > 0) ? warpsum[wid - 1] : 0;
    if (i < NN) g_off[i] = x - v + wprefix;
    if (tid == 1023) g_bsum[blockIdx.x] = wprefix + x;
}

// P2+P3 merged: every block redundantly warp-scans the 49 block sums (cheap),
// then adds its own block prefix and mirrors into g_cur.
__global__ __launch_bounds__(1024) void scan23_kernel() {
    __shared__ int s_pre[64];
    int tid = threadIdx.x, lane = tid & 31;
    if (tid < 32) {
        int v0 = (lane < NB_SCAN) ? g_bsum[lane] : 0;
        int x0 = v0;
        #pragma unroll
        for (int o = 1; o < 32; o <<= 1) {
            int t = __shfl_up_sync(0xFFFFFFFFu, x0, o);
            if (lane >= o) x0 += t;
        }
        int tot0 = __shfl_sync(0xFFFFFFFFu, x0, 31);
        int i1 = lane + 32;
        int v1 = (i1 < NB_SCAN) ? g_bsum[i1] : 0;
        int x1 = v1;
        #pragma unroll
        for (int o = 1; o < 32; o <<= 1) {
            int t = __shfl_up_sync(0xFFFFFFFFu, x1, o);
            if (lane >= o) x1 += t;
        }
        s_pre[lane] = x0 - v0;
        s_pre[i1] = x1 - v1 + tot0;
    }
    __syncthreads();
    int i = blockIdx.x * 1024 + tid;
    if (i < NN) {
        int o = g_off[i] + s_pre[blockIdx.x];
        g_off[i] = o;
        g_cur[i] = o;
    }
    if (i == 0) g_off[NN] = NE;
}

__global__ void scatter_kernel(const int* __restrict__ ei) {
    int idx = blockIdx.x * blockDim.x + threadIdx.x;
    if (idx < NE / 4) {
        int4 s4 = ((const int4*)ei)[idx];
        int4 d4 = ((const int4*)(ei + NE))[idx];
        if (d4.x >= 0 && d4.x < NN) g_esrc[atomicAdd(&g_cur[d4.x], 1)] = s4.x;
        if (d4.y >= 0 && d4.y < NN) g_esrc[atomicAdd(&g_cur[d4.y], 1)] = s4.y;
        if (d4.z >= 0 && d4.z < NN) g_esrc[atomicAdd(&g_cur[d4.z], 1)] = s4.z;
        if (d4.w >= 0 && d4.w < NN) g_esrc[atomicAdd(&g_cur[d4.w], 1)] = s4.w;
    }
}

// ---------------- bf16x2 tensor-core GEMM (R10 exact) ----------------------------
// M-tile 64, N=128. blockIdx.y: 0 -> g_lin16 (Wl, fp16 out), 1 -> g_root (Wr, fp32)
#define MT 64
#define SA 136
#define SB 136
#define A_ELEMS (64 * SA)
#define B_ELEMS (128 * SB)
#define GEMM_SMEM ((2 * A_ELEMS + 2 * B_ELEMS) * 2)   // 104448 bytes

__device__ __forceinline__ void mma_bf16(float* c, const uint32_t* a, const uint32_t* b) {
    asm volatile(
        "mma.sync.aligned.m16n8k16.row.col.f32.bf16.bf16.f32 "
        "{%0,%1,%2,%3}, {%4,%5,%6,%7}, {%8,%9}, {%0,%1,%2,%3};"
        : "+f"(c[0]), "+f"(c[1]), "+f"(c[2]), "+f"(c[3])
        : "r"(a[0]), "r"(a[1]), "r"(a[2]), "r"(a[3]), "r"(b[0]), "r"(b[1]));
}

__global__ __launch_bounds__(256, 2) void gemm2_kernel(int layer,
                                                       const float* __restrict__ X) {
    extern __shared__ uint16_t sm16[];
    uint16_t* Ah = sm16;
    uint16_t* Al = Ah + A_ELEMS;
    uint16_t* Bh = Al + A_ELEMS;
    uint16_t* Bl = Bh + B_ELEMS;

    const float* src = (layer == 0) ? X : ((layer == 1) ? g_bufA : g_bufB);
    int mat = layer * 2 + blockIdx.y;
    const __nv_bfloat16* wt_h = g_Wt_hi + mat * 16384;
    const __nv_bfloat16* wt_l = g_Wt_lo + mat * 16384;

    int tid = threadIdx.x, lane = tid & 31, wid = tid >> 5;
    int row0 = blockIdx.x * MT;

    #pragma unroll
    for (int i = 0; i < 8; i++) {
        int slot = tid + i * 256;
        int r = slot >> 5;
        int c = (slot & 31) << 2;
        float4 v = make_float4(0.f, 0.f, 0.f, 0.f);
        if (row0 + r < NN) v = *(const float4*)(src + (size_t)(row0 + r) * NF + c);
        uint16_t hx, lx, hy, ly, hz, lz, hw, lw;
        bsplit(v.x, hx, lx); bsplit(v.y, hy, ly);
        bsplit(v.z, hz, lz); bsplit(v.w, hw, lw);
        uint2 hp, lp;
        hp.x = pack2(hx, hy); hp.y = pack2(hz, hw);
        lp.x = pack2(lx, ly); lp.y = pack2(lz, lw);
        *(uint2*)&Ah[r * SA + c] = hp;
        *(uint2*)&Al[r * SA + c] = lp;
    }
    #pragma unroll
    for (int i = 0; i < 8; i++) {
        int slot = tid + i * 256;
        int n = slot >> 4;
        int c8 = (slot & 15) << 3;
        *(uint4*)&Bh[n * SB + c8] = *(const uint4*)&wt_h[n * 128 + c8];
        *(uint4*)&Bl[n * SB + c8] = *(const uint4*)&wt_l[n * 128 + c8];
    }
    __syncthreads();

    int warp_m = wid >> 2;
    int warp_n = wid & 3;
    int m_base = warp_m * 32;
    int n_base = warp_n * 32;
    int g = lane >> 2;
    int t = lane & 3;

    float c[2][4][4];
    #pragma unroll
    for (int mi = 0; mi < 2; mi++)
        #pragma unroll
        for (int ni = 0; ni < 4; ni++)
            #pragma unroll
            for (int j = 0; j < 4; j++) c[mi][ni][j] = 0.0f;

    #pragma unroll
    for (int ks = 0; ks < 8; ks++) {
        int k0 = ks * 16;
        uint32_t ah[2][4], al[2][4];
        #pragma unroll
        for (int mi = 0; mi < 2; mi++) {
            int r = m_base + mi * 16 + g;
            ah[mi][0] = *(const uint32_t*)&Ah[r * SA + k0 + 2 * t];
            ah[mi][1] = *(const uint32_t*)&Ah[(r + 8) * SA + k0 + 2 * t];
            ah[mi][2] = *(const uint32_t*)&Ah[r * SA + k0 + 2 * t + 8];
            ah[mi][3] = *(const uint32_t*)&Ah[(r + 8) * SA + k0 + 2 * t + 8];
            al[mi][0] = *(const uint32_t*)&Al[r * SA + k0 + 2 * t];
            al[mi][1] = *(const uint32_t*)&Al[(r + 8) * SA + k0 + 2 * t];
            al[mi][2] = *(const uint32_t*)&Al[r * SA + k0 + 2 * t + 8];
            al[mi][3] = *(const uint32_t*)&Al[(r + 8) * SA + k0 + 2 * t + 8];
        }
        uint32_t bh[4][2], blo[4][2];
        #pragma unroll
        for (int ni = 0; ni < 4; ni++) {
            int n = n_base + ni * 8 + g;
            bh[ni][0]  = *(const uint32_t*)&Bh[n * SB + k0 + 2 * t];
            bh[ni][1]  = *(const uint32_t*)&Bh[n * SB + k0 + 2 * t + 8];
            blo[ni][0] = *(const uint32_t*)&Bl[n * SB + k0 + 2 * t];
            blo[ni][1] = *(const uint32_t*)&Bl[n * SB + k0 + 2 * t + 8];
        }
        #pragma unroll
        for (int mi = 0; mi < 2; mi++)
            #pragma unroll
            for (int ni = 0; ni < 4; ni++) {
                mma_bf16(c[mi][ni], ah[mi], bh[ni]);
                mma_bf16(c[mi][ni], ah[mi], blo[ni]);
                mma_bf16(c[mi][ni], al[mi], bh[ni]);
            }
    }

    if (blockIdx.y == 0) {
        #pragma unroll
        for (int mi = 0; mi < 2; mi++) {
            int r0 = row0 + m_base + mi * 16 + g;
            int r1 = r0 + 8;
            #pragma unroll
            for (int ni = 0; ni < 4; ni++) {
                int col = n_base + ni * 8 + 2 * t;
                if (r0 < NN)
                    *(__half2*)(g_lin16 + (size_t)r0 * NF + col) =
                        __floats2half2_rn(c[mi][ni][0], c[mi][ni][1]);
                if (r1 < NN)
                    *(__half2*)(g_lin16 + (size_t)r1 * NF + col) =
                        __floats2half2_rn(c[mi][ni][2], c[mi][ni][3]);
            }
        }
    } else {
        #pragma unroll
        for (int mi = 0; mi < 2; mi++) {
            int r0 = row0 + m_base + mi * 16 + g;
            int r1 = r0 + 8;
            #pragma unroll
            for (int ni = 0; ni < 4; ni++) {
                int col = n_base + ni * 8 + 2 * t;
                if (r0 < NN)
                    *(float2*)(g_root + (size_t)r0 * NF + col) = make_float2(c[mi][ni][0], c[mi][ni][1]);
                if (r1 < NN)
                    *(float2*)(g_root + (size_t)r1 * NF + col) = make_float2(c[mi][ni][2], c[mi][ni][3]);
            }
        }
    }
}

// ---------------- aggregation: warp-per-node, fp16 gather, unroll 4 --------------
__global__ __launch_bounds__(256) void agg_kernel(int layer, int last,
                                                  const float* __restrict__ bl,
                                                  const float* __restrict__ Wout,
                                                  const int* __restrict__ batch) {
    float* xout = (layer == 1) ? g_bufB : g_bufA;
    int wid = threadIdx.x >> 5, lane = threadIdx.x & 31;
    int n = blockIdx.x * 8 + wid;
    if (n >= NN) return;
    int beg = g_off[n], end = g_off[n + 1];
    float4 acc = make_float4(0.f, 0.f, 0.f, 0.f);
    int e = beg;
    for (; e + 4 <= end; e += 4) {
        int s0 = g_esrc[e], s1 = g_esrc[e + 1], s2 = g_esrc[e + 2], s3 = g_esrc[e + 3];
        uint2 p0 = ((const uint2*)(g_lin16 + (size_t)s0 * NF))[lane];
        uint2 p1 = ((const uint2*)(g_lin16 + (size_t)s1 * NF))[lane];
        uint2 p2 = ((const uint2*)(g_lin16 + (size_t)s2 * NF))[lane];
        uint2 p3 = ((const uint2*)(g_lin16 + (size_t)s3 * NF))[lane];
        float2 a0 = __half22float2(*(__half2*)&p0.x), b0 = __half22float2(*(__half2*)&p0.y);
        float2 a1 = __half22float2(*(__half2*)&p1.x), b1 = __half22float2(*(__half2*)&p1.y);
        float2 a2 = __half22float2(*(__half2*)&p2.x), b2 = __half22float2(*(__half2*)&p2.y);
        float2 a3 = __half22float2(*(__half2*)&p3.x), b3 = __half22float2(*(__half2*)&p3.y);
        acc.x += (a0.x + a1.x) + (a2.x + a3.x);
        acc.y += (a0.y + a1.y) + (a2.y + a3.y);
        acc.z += (b0.x + b1.x) + (b2.x + b3.x);
        acc.w += (b0.y + b1.y) + (b2.y + b3.y);
    }
    for (; e < end; e++) {
        uint2 p = ((const uint2*)(g_lin16 + (size_t)g_esrc[e] * NF))[lane];
        float2 a = __half22float2(*(__half2*)&p.x);
        float2 b = __half22float2(*(__half2*)&p.y);
        acc.x += a.x; acc.y += a.y; acc.z += b.x; acc.w += b.y;
    }
    int deg = end - beg;
    float inv = (deg > 0) ? 1.0f / (float)deg : 0.0f;
    float4 bv = *(const float4*)(bl + lane * 4);
    float4 rv = *(const float4*)(g_root + (size_t)n * NF + lane * 4);
    float4 o;
    o.x = fmaxf(acc.x * inv + bv.x + rv.x, 0.0f);
    o.y = fmaxf(acc.y * inv + bv.y + rv.y, 0.0f);
    o.z = fmaxf(acc.z * inv + bv.z + rv.z, 0.0f);
    o.w = fmaxf(acc.w * inv + bv.w + rv.w, 0.0f);
    if (!last) {
        *(float4*)(xout + (size_t)n * NF + lane * 4) = o;
    } else {
        float4 w = *(const float4*)(Wout + lane * 4);
        float s = o.x * w.x + o.y * w.y + o.z * w.z + o.w * w.w;
        #pragma unroll
        for (int off = 16; off; off >>= 1) s += __shfl_xor_sync(0xFFFFFFFFu, s, off);
        if (lane == 0) {
            int b = batch[n];
            if (b >= 0 && b < NG) atomicAdd(&g_gsum[b], s);
        }
    }
}

__global__ void final_out_kernel(float* __restrict__ out, const float* __restrict__ b_out) {
    int g = blockIdx.x * blockDim.x + threadIdx.x;
    if (g < NG) {
        float c = fmaxf((float)g_gcnt[g], 1.0f);
        out[g] = g_gsum[g] / c + b_out[0];
    }
}

// ---------------- host launcher ----------------
extern "C" void kernel_launch(void* const* d_in, const int* in_sizes, int n_in,
                              void* d_out, int out_size) {
    const float* x     = (const float*)d_in[0];
    const int*   ei    = (const int*)d_in[1];
    const int*   batch = (const int*)d_in[2];
    const float* Wl[3] = { (const float*)d_in[3], (const float*)d_in[6], (const float*)d_in[9]  };
    const float* bl[3] = { (const float*)d_in[4], (const float*)d_in[7], (const float*)d_in[10] };
    const float* Wr[3] = { (const float*)d_in[5], (const float*)d_in[8], (const float*)d_in[11] };
    const float* W_out = (const float*)d_in[12];
    const float* b_out = (const float*)d_in[13];
    float* out = (float*)d_out;

    static int inited = 0;
    static cudaStream_t s2;
    static cudaEvent_t ev_fork, ev_join;
    if (!inited) {
        cudaFuncSetAttribute(gemm2_kernel, cudaFuncAttributeMaxDynamicSharedMemorySize,
                             GEMM_SMEM);
        cudaStreamCreateWithFlags(&s2, cudaStreamNonBlocking);
        cudaEventCreateWithFlags(&ev_fork, cudaEventDisableTiming);
        cudaEventCreateWithFlags(&ev_join, cudaEventDisableTiming);
        inited = 1;
    }

    // fork: CSR build chain on s2, concurrent with prep_w + gemm layer 0 on main
    cudaEventRecord(ev_fork, 0);
    cudaStreamWaitEvent(s2, ev_fork, 0);

    zero_kernel<<<(NN + 255) / 256, 256, 0, s2>>>();
    hist_kernel<<<(NE / 4 + 255) / 256, 256, 0, s2>>>(ei, batch);
    scan1_kernel<<<NB_SCAN, 1024, 0, s2>>>();
    scan23_kernel<<<NB_SCAN, 1024, 0, s2>>>();
    scatter_kernel<<<(NE / 4 + 255) / 256, 256, 0, s2>>>(ei);
    cudaEventRecord(ev_join, s2);

    dim3 wgrid(64, 6);
    prep_w_kernel<<<wgrid, 256>>>(Wl[0], Wr[0], Wl[1], Wr[1], Wl[2], Wr[2]);
    dim3 ggrid((NN + MT - 1) / MT, 2);
    gemm2_kernel<<<ggrid, 256, GEMM_SMEM>>>(0, x);

    // join before first aggregation (needs CSR)
    cudaStreamWaitEvent(0, ev_join, 0);

    agg_kernel<<<(NN + 7) / 8, 256>>>(0, 0, bl[0], W_out, batch);
    for (int l = 1; l < 3; l++) {
        gemm2_kernel<<<ggrid, 256, GEMM_SMEM>>>(l, x);
        agg_kernel<<<(NN + 7) / 8, 256>>>(l, (l == 2) ? 1 : 0, bl[l], W_out, batch);
    }

    final_out_kernel<<<(NG + 255) / 256, 256>>>(out, b_out);
}

// round 15
// speedup vs baseline: 1.1354x; 1.0121x over previous
#include <cuda_runtime.h>
#include <cuda_bf16.h>
#include <cuda_fp16.h>
#include <cstdint>
#include <cstddef>

#define NN 50000
#define NE 600000
#define NF 128
#define NG 500
#define NB_SCAN 49   // ceil(50000/1024)

// ---------------- device scratch (static, no allocation) ----------------
__device__ float  g_bufA[NN * NF];
__device__ float  g_bufB[NN * NF];
__device__ __half g_lin16[NN * NF];    // x @ Wl  (fp16, gather-only)
__device__ __half g_root16[NN * NF];   // x @ Wr  (fp16)
__device__ int    g_deg[NN];
__device__ int    g_off[NN + 1];
__device__ int    g_cur[NN];
__device__ int    g_esrc[NE];
__device__ float  g_gsum[NG];
__device__ int    g_gcnt[NG];
__device__ int    g_bsum[64];
// pre-split, pre-transposed weights: [mat][n][k] bf16, mat = layer*2 + (0:Wl,1:Wr)
__device__ __nv_bfloat16 g_Wt_hi[6 * 128 * 128];
__device__ __nv_bfloat16 g_Wt_lo[6 * 128 * 128];

__device__ __forceinline__ void bsplit(float v, uint16_t& h, uint16_t& l) {
    __nv_bfloat16 hb = __float2bfloat16_rn(v);
    float hf = __bfloat162float(hb);
    __nv_bfloat16 lb = __float2bfloat16_rn(v - hf);
    h = __bfloat16_as_ushort(hb);
    l = __bfloat16_as_ushort(lb);
}
__device__ __forceinline__ uint32_t pack2(uint16_t a, uint16_t b) {
    return (uint32_t)a | ((uint32_t)b << 16);
}

// ---------------- weight prep ----------------
__global__ void prep_w_kernel(const float* W0, const float* W1, const float* W2,
                              const float* W3, const float* W4, const float* W5) {
    const float* Ws[6] = { W0, W1, W2, W3, W4, W5 };
    int mat = blockIdx.y;
    const float* W = Ws[mat];
    int i = blockIdx.x * blockDim.x + threadIdx.x;   // 0..16383
    int k = i >> 7, n = i & 127;
    float v = W[i];
    uint16_t h, l;
    bsplit(v, h, l);
    int o = mat * 16384 + n * 128 + k;
    g_Wt_hi[o] = __ushort_as_bfloat16(h);
    g_Wt_lo[o] = __ushort_as_bfloat16(l);
}

// ---------------- CSR build ----------------
__global__ void zero_kernel() {
    int i = blockIdx.x * blockDim.x + threadIdx.x;
    if (i < NN) g_deg[i] = 0;
    if (i < NG) { g_gcnt[i] = 0; g_gsum[i] = 0.0f; }
}

__global__ void hist_kernel(const int* __restrict__ ei, const int* __restrict__ batch) {
    int idx = blockIdx.x * blockDim.x + threadIdx.x;
    if (idx < NE / 4) {
        int4 d4 = ((const int4*)(ei + NE))[idx];
        if (d4.x >= 0 && d4.x < NN) atomicAdd(&g_deg[d4.x], 1);
        if (d4.y >= 0 && d4.y < NN) atomicAdd(&g_deg[d4.y], 1);
        if (d4.z >= 0 && d4.z < NN) atomicAdd(&g_deg[d4.z], 1);
        if (d4.w >= 0 && d4.w < NN) atomicAdd(&g_deg[d4.w], 1);
    }
    if (idx < NN / 4) {
        int4 b4 = ((const int4*)batch)[idx];
        if (b4.x >= 0 && b4.x < NG) atomicAdd(&g_gcnt[b4.x], 1);
        if (b4.y >= 0 && b4.y < NG) atomicAdd(&g_gcnt[b4.y], 1);
        if (b4.z >= 0 && b4.z < NG) atomicAdd(&g_gcnt[b4.z], 1);
        if (b4.w >= 0 && b4.w < NG) atomicAdd(&g_gcnt[b4.w], 1);
    }
}

// P1: per-block local scan of 1024, emit block total
__global__ __launch_bounds__(1024) void scan1_kernel() {
    __shared__ int warpsum[32];
    int tid = threadIdx.x, lane = tid & 31, wid = tid >> 5;
    int i = blockIdx.x * 1024 + tid;
    int v = (i < NN) ? g_deg[i] : 0;
    int x = v;
    #pragma unroll
    for (int o = 1; o < 32; o <<= 1) {
        int t = __shfl_up_sync(0xFFFFFFFFu, x, o);
        if (lane >= o) x += t;
    }
    if (lane == 31) warpsum[wid] = x;
    __syncthreads();
    if (wid == 0) {
        int y = warpsum[lane];
        #pragma unroll
        for (int o = 1; o < 32; o <<= 1) {
            int t = __shfl_up_sync(0xFFFFFFFFu, y, o);
            if (lane >= o) y += t;
        }
        warpsum[lane] = y;
    }
    __syncthreads();
    int wprefix = (wid > 0) ? warpsum[wid - 1] : 0;
    if (i < NN) g_off[i] = x - v + wprefix;
    if (tid == 1023) g_bsum[blockIdx.x] = wprefix + x;
}

// P2+P3 merged: every block redundantly warp-scans the 49 block sums (cheap),
// then adds its own block prefix and mirrors into g_cur.
__global__ __launch_bounds__(1024) void scan23_kernel() {
    __shared__ int s_pre[64];
    int tid = threadIdx.x, lane = tid & 31;
    if (tid < 32) {
        int v0 = (lane < NB_SCAN) ? g_bsum[lane] : 0;
        int x0 = v0;
        #pragma unroll
        for (int o = 1; o < 32; o <<= 1) {
            int t = __shfl_up_sync(0xFFFFFFFFu, x0, o);
            if (lane >= o) x0 += t;
        }
        int tot0 = __shfl_sync(0xFFFFFFFFu, x0, 31);
        int i1 = lane + 32;
        int v1 = (i1 < NB_SCAN) ? g_bsum[i1] : 0;
        int x1 = v1;
        #pragma unroll
        for (int o = 1; o < 32; o <<= 1) {
            int t = __shfl_up_sync(0xFFFFFFFFu, x1, o);
            if (lane >= o) x1 += t;
        }
        s_pre[lane] = x0 - v0;
        s_pre[i1] = x1 - v1 + tot0;
    }
    __syncthreads();
    int i = blockIdx.x * 1024 + tid;
    if (i < NN) {
        int o = g_off[i] + s_pre[blockIdx.x];
        g_off[i] = o;
        g_cur[i] = o;
    }
    if (i == 0) g_off[NN] = NE;
}

__global__ void scatter_kernel(const int* __restrict__ ei) {
    int idx = blockIdx.x * blockDim.x + threadIdx.x;
    if (idx < NE / 4) {
        int4 s4 = ((const int4*)ei)[idx];
        int4 d4 = ((const int4*)(ei + NE))[idx];
        if (d4.x >= 0 && d4.x < NN) g_esrc[atomicAdd(&g_cur[d4.x], 1)] = s4.x;
        if (d4.y >= 0 && d4.y < NN) g_esrc[atomicAdd(&g_cur[d4.y], 1)] = s4.y;
        if (d4.z >= 0 && d4.z < NN) g_esrc[atomicAdd(&g_cur[d4.z], 1)] = s4.z;
        if (d4.w >= 0 && d4.w < NN) g_esrc[atomicAdd(&g_cur[d4.w], 1)] = s4.w;
    }
}

// ---------------- bf16x2 tensor-core GEMM ---------------------------------------
// M-tile 64, N=128. blockIdx.y: 0 -> g_lin16 (Wl), 1 -> g_root16 (Wr). fp16 out both.
#define MT 64
#define SA 136
#define SB 136
#define A_ELEMS (64 * SA)
#define B_ELEMS (128 * SB)
#define GEMM_SMEM ((2 * A_ELEMS + 2 * B_ELEMS) * 2)   // 104448 bytes

__device__ __forceinline__ void mma_bf16(float* c, const uint32_t* a, const uint32_t* b) {
    asm volatile(
        "mma.sync.aligned.m16n8k16.row.col.f32.bf16.bf16.f32 "
        "{%0,%1,%2,%3}, {%4,%5,%6,%7}, {%8,%9}, {%0,%1,%2,%3};"
        : "+f"(c[0]), "+f"(c[1]), "+f"(c[2]), "+f"(c[3])
        : "r"(a[0]), "r"(a[1]), "r"(a[2]), "r"(a[3]), "r"(b[0]), "r"(b[1]));
}

__global__ __launch_bounds__(256, 2) void gemm2_kernel(int layer,
                                                       const float* __restrict__ X) {
    extern __shared__ uint16_t sm16[];
    uint16_t* Ah = sm16;
    uint16_t* Al = Ah + A_ELEMS;
    uint16_t* Bh = Al + A_ELEMS;
    uint16_t* Bl = Bh + B_ELEMS;

    const float* src = (layer == 0) ? X : ((layer == 1) ? g_bufA : g_bufB);
    __half* outp = blockIdx.y ? g_root16 : g_lin16;
    int mat = layer * 2 + blockIdx.y;
    const __nv_bfloat16* wt_h = g_Wt_hi + mat * 16384;
    const __nv_bfloat16* wt_l = g_Wt_lo + mat * 16384;

    int tid = threadIdx.x, lane = tid & 31, wid = tid >> 5;
    int row0 = blockIdx.x * MT;

    #pragma unroll
    for (int i = 0; i < 8; i++) {
        int slot = tid + i * 256;
        int r = slot >> 5;
        int c = (slot & 31) << 2;
        float4 v = make_float4(0.f, 0.f, 0.f, 0.f);
        if (row0 + r < NN) v = *(const float4*)(src + (size_t)(row0 + r) * NF + c);
        uint16_t hx, lx, hy, ly, hz, lz, hw, lw;
        bsplit(v.x, hx, lx); bsplit(v.y, hy, ly);
        bsplit(v.z, hz, lz); bsplit(v.w, hw, lw);
        uint2 hp, lp;
        hp.x = pack2(hx, hy); hp.y = pack2(hz, hw);
        lp.x = pack2(lx, ly); lp.y = pack2(lz, lw);
        *(uint2*)&Ah[r * SA + c] = hp;
        *(uint2*)&Al[r * SA + c] = lp;
    }
    #pragma unroll
    for (int i = 0; i < 8; i++) {
        int slot = tid + i * 256;
        int n = slot >> 4;
        int c8 = (slot & 15) << 3;
        *(uint4*)&Bh[n * SB + c8] = *(const uint4*)&wt_h[n * 128 + c8];
        *(uint4*)&Bl[n * SB + c8] = *(const uint4*)&wt_l[n * 128 + c8];
    }
    __syncthreads();

    int warp_m = wid >> 2;
    int warp_n = wid & 3;
    int m_base = warp_m * 32;
    int n_base = warp_n * 32;
    int g = lane >> 2;
    int t = lane & 3;

    float c[2][4][4];
    #pragma unroll
    for (int mi = 0; mi < 2; mi++)
        #pragma unroll
        for (int ni = 0; ni < 4; ni++)
            #pragma unroll
            for (int j = 0; j < 4; j++) c[mi][ni][j] = 0.0f;

    #pragma unroll
    for (int ks = 0; ks < 8; ks++) {
        int k0 = ks * 16;
        uint32_t ah[2][4], al[2][4];
        #pragma unroll
        for (int mi = 0; mi < 2; mi++) {
            int r = m_base + mi * 16 + g;
            ah[mi][0] = *(const uint32_t*)&Ah[r * SA + k0 + 2 * t];
            ah[mi][1] = *(const uint32_t*)&Ah[(r + 8) * SA + k0 + 2 * t];
            ah[mi][2] = *(const uint32_t*)&Ah[r * SA + k0 + 2 * t + 8];
            ah[mi][3] = *(const uint32_t*)&Ah[(r + 8) * SA + k0 + 2 * t + 8];
            al[mi][0] = *(const uint32_t*)&Al[r * SA + k0 + 2 * t];
            al[mi][1] = *(const uint32_t*)&Al[(r + 8) * SA + k0 + 2 * t];
            al[mi][2] = *(const uint32_t*)&Al[r * SA + k0 + 2 * t + 8];
            al[mi][3] = *(const uint32_t*)&Al[(r + 8) * SA + k0 + 2 * t + 8];
        }
        uint32_t bh[4][2], blo[4][2];
        #pragma unroll
        for (int ni = 0; ni < 4; ni++) {
            int n = n_base + ni * 8 + g;
            bh[ni][0]  = *(const uint32_t*)&Bh[n * SB + k0 + 2 * t];
            bh[ni][1]  = *(const uint32_t*)&Bh[n * SB + k0 + 2 * t + 8];
            blo[ni][0] = *(const uint32_t*)&Bl[n * SB + k0 + 2 * t];
            blo[ni][1] = *(const uint32_t*)&Bl[n * SB + k0 + 2 * t + 8];
        }
        #pragma unroll
        for (int mi = 0; mi < 2; mi++)
            #pragma unroll
            for (int ni = 0; ni < 4; ni++) {
                mma_bf16(c[mi][ni], ah[mi], bh[ni]);
                mma_bf16(c[mi][ni], ah[mi], blo[ni]);
                mma_bf16(c[mi][ni], al[mi], bh[ni]);
            }
    }

    // unified fp16 epilogue (both outputs)
    #pragma unroll
    for (int mi = 0; mi < 2; mi++) {
        int r0 = row0 + m_base + mi * 16 + g;
        int r1 = r0 + 8;
        #pragma unroll
        for (int ni = 0; ni < 4; ni++) {
            int col = n_base + ni * 8 + 2 * t;
            if (r0 < NN)
                *(__half2*)(outp + (size_t)r0 * NF + col) =
                    __floats2half2_rn(c[mi][ni][0], c[mi][ni][1]);
            if (r1 < NN)
                *(__half2*)(outp + (size_t)r1 * NF + col) =
                    __floats2half2_rn(c[mi][ni][2], c[mi][ni][3]);
        }
    }
}

// ---------------- aggregation: warp-per-node, fp16 gather + fp16 root ------------
__global__ __launch_bounds__(256) void agg_kernel(int layer, int last,
                                                  const float* __restrict__ bl,
                                                  const float* __restrict__ Wout,
                                                  const int* __restrict__ batch) {
    float* xout = (layer == 1) ? g_bufB : g_bufA;
    int wid = threadIdx.x >> 5, lane = threadIdx.x & 31;
    int n = blockIdx.x * 8 + wid;
    if (n >= NN) return;
    int beg = g_off[n], end = g_off[n + 1];
    float4 acc = make_float4(0.f, 0.f, 0.f, 0.f);
    int e = beg;
    for (; e + 4 <= end; e += 4) {
        int s0 = g_esrc[e], s1 = g_esrc[e + 1], s2 = g_esrc[e + 2], s3 = g_esrc[e + 3];
        uint2 p0 = ((const uint2*)(g_lin16 + (size_t)s0 * NF))[lane];
        uint2 p1 = ((const uint2*)(g_lin16 + (size_t)s1 * NF))[lane];
        uint2 p2 = ((const uint2*)(g_lin16 + (size_t)s2 * NF))[lane];
        uint2 p3 = ((const uint2*)(g_lin16 + (size_t)s3 * NF))[lane];
        float2 a0 = __half22float2(*(__half2*)&p0.x), b0 = __half22float2(*(__half2*)&p0.y);
        float2 a1 = __half22float2(*(__half2*)&p1.x), b1 = __half22float2(*(__half2*)&p1.y);
        float2 a2 = __half22float2(*(__half2*)&p2.x), b2 = __half22float2(*(__half2*)&p2.y);
        float2 a3 = __half22float2(*(__half2*)&p3.x), b3 = __half22float2(*(__half2*)&p3.y);
        acc.x += (a0.x + a1.x) + (a2.x + a3.x);
        acc.y += (a0.y + a1.y) + (a2.y + a3.y);
        acc.z += (b0.x + b1.x) + (b2.x + b3.x);
        acc.w += (b0.y + b1.y) + (b2.y + b3.y);
    }
    for (; e < end; e++) {
        uint2 p = ((const uint2*)(g_lin16 + (size_t)g_esrc[e] * NF))[lane];
        float2 a = __half22float2(*(__half2*)&p.x);
        float2 b = __half22float2(*(__half2*)&p.y);
        acc.x += a.x; acc.y += a.y; acc.z += b.x; acc.w += b.y;
    }
    int deg = end - beg;
    float inv = (deg > 0) ? 1.0f / (float)deg : 0.0f;
    float4 bv = *(const float4*)(bl + lane * 4);
    uint2 pr = ((const uint2*)(g_root16 + (size_t)n * NF))[lane];
    float2 r01 = __half22float2(*(__half2*)&pr.x);
    float2 r23 = __half22float2(*(__half2*)&pr.y);
    float4 o;
    o.x = fmaxf(acc.x * inv + bv.x + r01.x, 0.0f);
    o.y = fmaxf(acc.y * inv + bv.y + r01.y, 0.0f);
    o.z = fmaxf(acc.z * inv + bv.z + r23.x, 0.0f);
    o.w = fmaxf(acc.w * inv + bv.w + r23.y, 0.0f);
    if (!last) {
        *(float4*)(xout + (size_t)n * NF + lane * 4) = o;
    } else {
        float4 w = *(const float4*)(Wout + lane * 4);
        float s = o.x * w.x + o.y * w.y + o.z * w.z + o.w * w.w;
        #pragma unroll
        for (int off = 16; off; off >>= 1) s += __shfl_xor_sync(0xFFFFFFFFu, s, off);
        if (lane == 0) {
            int b = batch[n];
            if (b >= 0 && b < NG) atomicAdd(&g_gsum[b], s);
        }
    }
}

__global__ void final_out_kernel(float* __restrict__ out, const float* __restrict__ b_out) {
    int g = blockIdx.x * blockDim.x + threadIdx.x;
    if (g < NG) {
        float c = fmaxf((float)g_gcnt[g], 1.0f);
        out[g] = g_gsum[g] / c + b_out[0];
    }
}

// ---------------- host launcher ----------------
extern "C" void kernel_launch(void* const* d_in, const int* in_sizes, int n_in,
                              void* d_out, int out_size) {
    const float* x     = (const float*)d_in[0];
    const int*   ei    = (const int*)d_in[1];
    const int*   batch = (const int*)d_in[2];
    const float* Wl[3] = { (const float*)d_in[3], (const float*)d_in[6], (const float*)d_in[9]  };
    const float* bl[3] = { (const float*)d_in[4], (const float*)d_in[7], (const float*)d_in[10] };
    const float* Wr[3] = { (const float*)d_in[5], (const float*)d_in[8], (const float*)d_in[11] };
    const float* W_out = (const float*)d_in[12];
    const float* b_out = (const float*)d_in[13];
    float* out = (float*)d_out;

    static int inited = 0;
    static cudaStream_t s2;
    static cudaEvent_t ev_fork, ev_join;
    if (!inited) {
        cudaFuncSetAttribute(gemm2_kernel, cudaFuncAttributeMaxDynamicSharedMemorySize,
                             GEMM_SMEM);
        cudaStreamCreateWithFlags(&s2, cudaStreamNonBlocking);
        cudaEventCreateWithFlags(&ev_fork, cudaEventDisableTiming);
        cudaEventCreateWithFlags(&ev_join, cudaEventDisableTiming);
        inited = 1;
    }

    // fork: CSR build chain on s2, concurrent with prep_w + gemm layer 0 on main
    cudaEventRecord(ev_fork, 0);
    cudaStreamWaitEvent(s2, ev_fork, 0);

    zero_kernel<<<(NN + 255) / 256, 256, 0, s2>>>();
    hist_kernel<<<(NE / 4 + 255) / 256, 256, 0, s2>>>(ei, batch);
    scan1_kernel<<<NB_SCAN, 1024, 0, s2>>>();
    scan23_kernel<<<NB_SCAN, 1024, 0, s2>>>();
    scatter_kernel<<<(NE / 4 + 255) / 256, 256, 0, s2>>>(ei);
    cudaEventRecord(ev_join, s2);

    dim3 wgrid(64, 6);
    prep_w_kernel<<<wgrid, 256>>>(Wl[0], Wr[0], Wl[1], Wr[1], Wl[2], Wr[2]);
    dim3 ggrid((NN + MT - 1) / MT, 2);
    gemm2_kernel<<<ggrid, 256, GEMM_SMEM>>>(0, x);

    // join before first aggregation (needs CSR)
    cudaStreamWaitEvent(0, ev_join, 0);

    agg_kernel<<<(NN + 7) / 8, 256>>>(0, 0, bl[0], W_out, batch);
    for (int l = 1; l < 3; l++) {
        gemm2_kernel<<<ggrid, 256, GEMM_SMEM>>>(l, x);
        agg_kernel<<<(NN + 7) / 8, 256>>>(l, (l == 2) ? 1 : 0, bl[l], W_out, batch);
    }

    final_out_kernel<<<(NG + 255) / 256, 256>>>(out, b_out);
}